// round 6
// baseline (speedup 1.0000x reference)
#include <cuda_runtime.h>
#include <cuda_bf16.h>

// Output: out[b,c,h,w] = x[b,c, 2h+o, 2w+p], where (o,p)=divmod(i,2).
// B*C = 24 images, in 2048x2048, out 1024x1024.
// Persistent grid-stride form: 1536 blocks x 256 threads, each thread does
// exactly 16 output-float4 iterations, unrolled x4 so ptxas front-batches
// 4 independent 256-bit loads (MLP=4/warp) before the dependent stores.
// Loads: ld.global.nc.v8.f32 (one coalesced 1024B request per warp-load).
// Stores: __stcs (evict-first; write stream must not displace read sectors).

static constexpr int H_IN  = 2048;
static constexpr int W_IN  = 2048;
static constexpr int H_OUT = 1024;
static constexpr int W_OUT = 1024;
static constexpr int W_OUT4 = W_OUT / 4;              // 256 float4 per out row
static constexpr long IMG_IN  = (long)H_IN * W_IN;    // 4,194,304 floats

static constexpr int  BLOCKS  = 1536;
static constexpr int  THREADS = 256;
static constexpr long STRIDE  = (long)BLOCKS * THREADS;   // 393,216
// total4 = 6,291,456 = STRIDE * 16 exactly.

__global__ void __launch_bounds__(THREADS) slice_stride2_kernel(
    const float* __restrict__ x,
    const int* __restrict__ ip,
    float4* __restrict__ out,
    long total4)
{
    const long t0 = (long)blockIdx.x * THREADS + threadIdx.x;

    const int iv = ip[0];
    const int o = (iv >> 1) & 1;
    const int p = iv & 1;

    #pragma unroll 4
    for (long t = t0; t < total4; t += STRIDE) {
        // t -> (img, out_row, out_col4). W_OUT4=256, H_OUT=1024 (pow2).
        const int  w4  = (int)(t & (W_OUT4 - 1));
        const int  row = (int)((t >> 8) & (H_OUT - 1));
        const long img = t >> 18;

        const float* src = x + img * IMG_IN
                             + (long)(2 * row + o) * W_IN + (long)w4 * 8;

        float f0, f1, f2, f3, f4, f5, f6, f7;
        asm volatile(
            "ld.global.nc.v8.f32 {%0, %1, %2, %3, %4, %5, %6, %7}, [%8];"
            : "=f"(f0), "=f"(f1), "=f"(f2), "=f"(f3),
              "=f"(f4), "=f"(f5), "=f"(f6), "=f"(f7)
            : "l"(src));

        float4 r;
        if (p == 0) { r.x = f0; r.y = f2; r.z = f4; r.w = f6; }
        else        { r.x = f1; r.y = f3; r.z = f5; r.w = f7; }

        __stcs(out + t, r);
    }
}

extern "C" void kernel_launch(void* const* d_in, const int* in_sizes, int n_in,
                              void* d_out, int out_size)
{
    const float* x  = (const float*)d_in[0];
    const int*   ip = (const int*)d_in[1];
    float4* out = (float4*)d_out;

    const long total4 = (long)out_size / 4;   // 6,291,456
    slice_stride2_kernel<<<BLOCKS, THREADS>>>(x, ip, out, total4);
}

// round 7
// speedup vs baseline: 1.0065x; 1.0065x over previous
#include <cuda_runtime.h>
#include <cuda_bf16.h>

// Output: out[b,c,h,w] = x[b,c, 2h+o, 2w+p], where (o,p)=divmod(i,2).
// B*C = 24 images, in 2048x2048, out 1024x1024.
// Each thread: TWO 256-bit loads (ld.global.nc.v8.f32) covering 64B of the
// source row, lane-select by p, ONE 256-bit streaming store
// (st.global.cs.v8.f32) of 32B of output. Warp-level: two coalesced 1024B
// read requests + one coalesced 1024B write request per iteration.

static constexpr int H_IN  = 2048;
static constexpr int W_IN  = 2048;
static constexpr int H_OUT = 1024;
static constexpr int W_OUT = 1024;
static constexpr int W_OUT8 = W_OUT / 8;              // 128 v8-groups per out row
static constexpr long IMG_IN  = (long)H_IN * W_IN;    // 4,194,304 floats

__global__ void __launch_bounds__(256) slice_stride2_kernel(
    const float* __restrict__ x,
    const int* __restrict__ ip,
    float* __restrict__ out,
    long total8)
{
    long t = (long)blockIdx.x * blockDim.x + threadIdx.x;
    if (t >= total8) return;

    const int iv = ip[0];
    const int o = (iv >> 1) & 1;
    const int p = iv & 1;

    // t -> (img, out_row, out_group8). W_OUT8=128 (7 bits), H_OUT=1024 (10 bits).
    const int  g8  = (int)(t & (W_OUT8 - 1));
    const int  row = (int)((t >> 7) & (H_OUT - 1));
    const long img = t >> 17;

    const float* src = x + img * IMG_IN
                         + (long)(2 * row + o) * W_IN + (long)g8 * 16;

    // Two independent 256-bit loads: 16 consecutive source floats.
    float a0, a1, a2, a3, a4, a5, a6, a7;
    float b0, b1, b2, b3, b4, b5, b6, b7;
    asm volatile(
        "ld.global.nc.v8.f32 {%0, %1, %2, %3, %4, %5, %6, %7}, [%8];"
        : "=f"(a0), "=f"(a1), "=f"(a2), "=f"(a3),
          "=f"(a4), "=f"(a5), "=f"(a6), "=f"(a7)
        : "l"(src));
    asm volatile(
        "ld.global.nc.v8.f32 {%0, %1, %2, %3, %4, %5, %6, %7}, [%8];"
        : "=f"(b0), "=f"(b1), "=f"(b2), "=f"(b3),
          "=f"(b4), "=f"(b5), "=f"(b6), "=f"(b7)
        : "l"(src + 8));

    float r0, r1, r2, r3, r4, r5, r6, r7;
    if (p == 0) {
        r0 = a0; r1 = a2; r2 = a4; r3 = a6;
        r4 = b0; r5 = b2; r6 = b4; r7 = b6;
    } else {
        r0 = a1; r1 = a3; r2 = a5; r3 = a7;
        r4 = b1; r5 = b3; r6 = b5; r7 = b7;
    }

    // One 256-bit streaming store: 8 consecutive output floats (32B aligned).
    float* dst = out + t * 8;
    asm volatile(
        "st.global.cs.v8.f32 [%0], {%1, %2, %3, %4, %5, %6, %7, %8};"
        :: "l"(dst),
           "f"(r0), "f"(r1), "f"(r2), "f"(r3),
           "f"(r4), "f"(r5), "f"(r6), "f"(r7)
        : "memory");
}

extern "C" void kernel_launch(void* const* d_in, const int* in_sizes, int n_in,
                              void* d_out, int out_size)
{
    const float* x  = (const float*)d_in[0];
    const int*   ip = (const int*)d_in[1];
    float* out = (float*)d_out;

    const long total8 = (long)out_size / 8;   // 3,145,728
    const int threads = 256;
    const int blocks = (int)((total8 + threads - 1) / threads);
    slice_stride2_kernel<<<blocks, threads>>>(x, ip, out, total8);
}